// round 1
// baseline (speedup 1.0000x reference)
#include <cuda_runtime.h>
#include <math.h>

#define BATCH   4096
#define NROWS   8192
#define DIM     512
#define TAU_INV 10.0f

#define TM 128
#define TN 128
#define TK 16
#define CSPLIT 16
#define TILES_PER_SPLIT ((NROWS / TN) / CSPLIT)   // 4

// Scratch (device globals: no runtime allocation)
__device__ float        d_Xn[(size_t)NROWS * DIM];   // normalized [A;B], 16 MB
__device__ float        d_gsum[NROWS];               // sum of exp(10c-10) over j != r
__device__ unsigned int d_gmax[NROWS];               // encoded row max of c (j != r)
__device__ float        d_gd[NROWS];                 // partner dot c = G[r, r^4096]
__device__ float        d_loss;
__device__ int          d_correct;

// Order-preserving float<->uint encoding for atomicMax on float
__device__ __forceinline__ unsigned int fenc(float f) {
    unsigned int u = __float_as_uint(f);
    return (u & 0x80000000u) ? ~u : (u | 0x80000000u);
}
__device__ __forceinline__ float fdec(unsigned int u) {
    u = (u & 0x80000000u) ? (u & 0x7FFFFFFFu) : ~u;
    return __uint_as_float(u);
}

// ---------------------------------------------------------------------------
__global__ void zero_kernel() {
    int i = blockIdx.x * blockDim.x + threadIdx.x;
    if (i < NROWS) {
        d_gsum[i] = 0.0f;
        d_gmax[i] = 0u;        // 0 < fenc(x) for all finite x
        d_gd[i]   = 0.0f;
    }
    if (i == 0) { d_loss = 0.0f; d_correct = 0; }
}

// ---------------------------------------------------------------------------
// One block per row of X. Row r<BATCH comes from view_a, else view_b.
__global__ void norm_kernel(const float* __restrict__ a,
                            const float* __restrict__ b) {
    int r = blockIdx.x;
    const float* src = (r < BATCH) ? a + (size_t)r * DIM
                                   : b + (size_t)(r - BATCH) * DIM;
    int t = threadIdx.x;   // 128 threads, 4 floats each
    float4 v = reinterpret_cast<const float4*>(src)[t];
    float ss = v.x * v.x + v.y * v.y + v.z * v.z + v.w * v.w;
    #pragma unroll
    for (int o = 16; o > 0; o >>= 1) ss += __shfl_xor_sync(0xffffffffu, ss, o);
    __shared__ float ws[4];
    if ((t & 31) == 0) ws[t >> 5] = ss;
    __syncthreads();
    float tot = ws[0] + ws[1] + ws[2] + ws[3];
    float scale = 1.0f / fmaxf(sqrtf(tot), 1e-12f);
    v.x *= scale; v.y *= scale; v.z *= scale; v.w *= scale;
    reinterpret_cast<float4*>(d_Xn + (size_t)r * DIM)[t] = v;
}

// ---------------------------------------------------------------------------
// Fused gram + softmax-stat kernel.
// Grid (NROWS/TM, CSPLIT), 256 threads. Block computes G tile rows
// [i0, i0+128) against TILES_PER_SPLIT column tiles of 128; epilogue
// accumulates per-row sum(exp(10c-10)) and max(c) with the self-diagonal
// excluded, and writes the partner dot (col == row ^ 4096) directly.
__global__ __launch_bounds__(256) void gram_kernel() {
    __shared__ float As[TK][TM + 4];
    __shared__ float Bs[TK][TN + 4];

    int tid = threadIdx.x;
    int tx = tid & 15;         // column group
    int ty = tid >> 4;         // row group
    int i0 = blockIdx.x * TM;

    float psum[8];
    float pmax[8];
    #pragma unroll
    for (int i = 0; i < 8; i++) { psum[i] = 0.0f; pmax[i] = -2.0f; }

    int lr = tid >> 2;               // 0..63 (row within half-tile)
    int lq = (tid & 3) * 4;          // k offset (float4 granule)

    for (int ct = 0; ct < TILES_PER_SPLIT; ct++) {
        int j0 = (blockIdx.y * TILES_PER_SPLIT + ct) * TN;

        float acc[8][8];
        #pragma unroll
        for (int i = 0; i < 8; i++)
            #pragma unroll
            for (int j = 0; j < 8; j++) acc[i][j] = 0.0f;

        for (int k0 = 0; k0 < DIM; k0 += TK) {
            float4 va0 = *reinterpret_cast<const float4*>(
                &d_Xn[(size_t)(i0 + lr)      * DIM + k0 + lq]);
            float4 va1 = *reinterpret_cast<const float4*>(
                &d_Xn[(size_t)(i0 + lr + 64) * DIM + k0 + lq]);
            float4 vb0 = *reinterpret_cast<const float4*>(
                &d_Xn[(size_t)(j0 + lr)      * DIM + k0 + lq]);
            float4 vb1 = *reinterpret_cast<const float4*>(
                &d_Xn[(size_t)(j0 + lr + 64) * DIM + k0 + lq]);

            __syncthreads();   // previous iteration's consumers done

            As[lq + 0][lr] = va0.x; As[lq + 1][lr] = va0.y;
            As[lq + 2][lr] = va0.z; As[lq + 3][lr] = va0.w;
            As[lq + 0][lr + 64] = va1.x; As[lq + 1][lr + 64] = va1.y;
            As[lq + 2][lr + 64] = va1.z; As[lq + 3][lr + 64] = va1.w;
            Bs[lq + 0][lr] = vb0.x; Bs[lq + 1][lr] = vb0.y;
            Bs[lq + 2][lr] = vb0.z; Bs[lq + 3][lr] = vb0.w;
            Bs[lq + 0][lr + 64] = vb1.x; Bs[lq + 1][lr + 64] = vb1.y;
            Bs[lq + 2][lr + 64] = vb1.z; Bs[lq + 3][lr + 64] = vb1.w;

            __syncthreads();

            #pragma unroll
            for (int kk = 0; kk < TK; kk++) {
                float af[8], bf[8];
                #pragma unroll
                for (int i = 0; i < 8; i++) af[i] = As[kk][ty * 8 + i];
                #pragma unroll
                for (int j = 0; j < 8; j++) bf[j] = Bs[kk][tx * 8 + j];
                #pragma unroll
                for (int i = 0; i < 8; i++)
                    #pragma unroll
                    for (int j = 0; j < 8; j++)
                        acc[i][j] = fmaf(af[i], bf[j], acc[i][j]);
            }
        }

        // Epilogue: fixed-max online softmax stats (logits in [-10,10])
        #pragma unroll
        for (int ri = 0; ri < 8; ri++) {
            int grow = i0 + ty * 8 + ri;
            int prt  = grow ^ BATCH;     // partner column
            #pragma unroll
            for (int cj = 0; cj < 8; cj++) {
                int gcol = j0 + tx * 8 + cj;
                float c = acc[ri][cj];
                if (gcol != grow) {
                    psum[ri] += __expf(fmaf(TAU_INV, c, -TAU_INV));
                    pmax[ri]  = fmaxf(pmax[ri], c);
                    if (gcol == prt) d_gd[grow] = c;   // exactly one writer globally
                }
            }
        }
    }

    // Cross-tx reduction in smem (reuse tile buffers, stride TM+1 = conflict-free)
    __syncthreads();
    float* rs = &As[0][0];   // 16*129 = 2064 <= 16*132
    float* rm = &Bs[0][0];
    #pragma unroll
    for (int ri = 0; ri < 8; ri++) {
        int lrow = ty * 8 + ri;
        rs[tx * (TM + 1) + lrow] = psum[ri];
        rm[tx * (TM + 1) + lrow] = pmax[ri];
    }
    __syncthreads();
    if (tid < TM) {
        float s = 0.0f, m = -2.0f;
        #pragma unroll
        for (int x = 0; x < 16; x++) {
            s += rs[x * (TM + 1) + tid];
            m  = fmaxf(m, rm[x * (TM + 1) + tid]);
        }
        int grow = i0 + tid;
        atomicAdd(&d_gsum[grow], s);
        atomicMax(&d_gmax[grow], fenc(m));
    }
}

// ---------------------------------------------------------------------------
__global__ void finalize_kernel() {
    int r = blockIdx.x * blockDim.x + threadIdx.x;
    float lossv = 0.0f;
    int corr = 0;
    if (r < NROWS) {
        float s = d_gsum[r];
        float d = d_gd[r];
        // lse = 10 + log(sum exp(10c - 10));  label logit = 10*d
        lossv = (TAU_INV + __logf(s)) - TAU_INV * d;
        if (r < BATCH) {
            float m = fdec(d_gmax[r]);
            corr = (d >= m) ? 1 : 0;   // partner is included in max scan
        }
    }
    #pragma unroll
    for (int o = 16; o > 0; o >>= 1) {
        lossv += __shfl_xor_sync(0xffffffffu, lossv, o);
        corr  += __shfl_xor_sync(0xffffffffu, corr, o);
    }
    __shared__ float sl[8];
    __shared__ int   sc[8];
    int w = threadIdx.x >> 5, lane = threadIdx.x & 31;
    if (lane == 0) { sl[w] = lossv; sc[w] = corr; }
    __syncthreads();
    if (threadIdx.x == 0) {
        float L = 0.0f; int C = 0;
        #pragma unroll
        for (int i = 0; i < 8; i++) { L += sl[i]; C += sc[i]; }
        atomicAdd(&d_loss, L);
        atomicAdd(&d_correct, C);
    }
}

// ---------------------------------------------------------------------------
__global__ void writeout_kernel(float* out, int out_size) {
    if (threadIdx.x == 0) {
        out[0] = d_loss / (float)NROWS;
        if (out_size > 1)
            out[1] = 100.0f * (float)d_correct / (float)BATCH;
    }
}

// ---------------------------------------------------------------------------
extern "C" void kernel_launch(void* const* d_in, const int* in_sizes, int n_in,
                              void* d_out, int out_size) {
    const float* a = (const float*)d_in[0];
    const float* b = (const float*)d_in[1];
    float* out = (float*)d_out;

    zero_kernel<<<(NROWS + 255) / 256, 256>>>();
    norm_kernel<<<NROWS, 128>>>(a, b);
    dim3 grid(NROWS / TM, CSPLIT);
    gram_kernel<<<grid, 256>>>();
    finalize_kernel<<<NROWS / 256, 256>>>();
    writeout_kernel<<<1, 32>>>(out, out_size);
}